// round 9
// baseline (speedup 1.0000x reference)
#include <cuda_runtime.h>
#include <cuda_bf16.h>
#include <cstdint>
#include <math.h>

// ================= problem constants =================
#define B_    4
#define S_    512
#define NS_   8192
#define MAXW  16
#define H_    256
#define NH_   4
#define DH_   64
#define FF_   1024
#define NSPAN (B_*NS_)          // 32768
#define NEGV  (-1000000000.0f)

// ================= device scratch =================
__device__ float g_TR[B_*S_*H_];
__device__ float g_QK[NH_*H_];
__device__ float g_BO[H_];
__device__ float g_Vtok[B_*S_*H_];               // TR @ w_v^T  (2 MB)
__device__ float4 g_Ltok[B_*S_];                 // per-token logits (4 heads)
__device__ float g_T1[(size_t)NSPAN*H_];
__device__ __nv_bfloat16 g_Ctxh[(size_t)NSPAN*H_];
__device__ __nv_bfloat16 g_Ctxl[(size_t)NSPAN*H_];
__device__ __nv_bfloat16 g_Yh[(size_t)NSPAN*H_];
__device__ __nv_bfloat16 g_Yl[(size_t)NSPAN*H_];
__device__ __nv_bfloat16 g_Fh[(size_t)NSPAN*FF_];
__device__ __nv_bfloat16 g_Fl[(size_t)NSPAN*FF_];
__device__ __nv_bfloat16 g_WOh[H_*H_];           // w_o split, [n][k]
__device__ __nv_bfloat16 g_WOl[H_*H_];
__device__ __nv_bfloat16 g_W1Th[FF_*H_];         // w1^T split  [1024][256]
__device__ __nv_bfloat16 g_W1Tl[FF_*H_];
__device__ __nv_bfloat16 g_W2Th[H_*FF_];         // w2^T split  [256][1024]
__device__ __nv_bfloat16 g_W2Tl[H_*FF_];
__device__ int g_mask_is_byte;

__device__ __forceinline__ void split_bf16(float x, __nv_bfloat16& h, __nv_bfloat16& l) {
    h = __float2bfloat16(x);
    l = __float2bfloat16(x - __bfloat162float(h));
}

// ================= small PTX helpers =================
__device__ __forceinline__ uint32_t smem_u32(const void* p) {
    uint32_t a;
    asm("{ .reg .u64 t; cvta.to.shared.u64 t, %1; cvt.u32.u64 %0, t; }" : "=r"(a) : "l"(p));
    return a;
}
__device__ __forceinline__ void cp16(uint32_t s, const void* g) {
    asm volatile("cp.async.cg.shared.global [%0], [%1], 16;" :: "r"(s), "l"(g));
}
#define CP_COMMIT() asm volatile("cp.async.commit_group;" ::: "memory")
#define CP_WAIT(n)  asm volatile("cp.async.wait_group %0;" :: "n"(n) : "memory")

__device__ __forceinline__ void ldsm4(uint32_t& r0, uint32_t& r1, uint32_t& r2, uint32_t& r3, uint32_t a) {
    asm volatile("ldmatrix.sync.aligned.m8n8.x4.shared.b16 {%0,%1,%2,%3}, [%4];"
                 : "=r"(r0), "=r"(r1), "=r"(r2), "=r"(r3) : "r"(a));
}
__device__ __forceinline__ void mma16816(float* d, uint32_t a0, uint32_t a1, uint32_t a2, uint32_t a3,
                                         uint32_t b0, uint32_t b1) {
    asm volatile("mma.sync.aligned.m16n8k16.row.col.f32.bf16.bf16.f32 "
                 "{%0,%1,%2,%3}, {%4,%5,%6,%7}, {%8,%9}, {%0,%1,%2,%3};"
                 : "+f"(d[0]), "+f"(d[1]), "+f"(d[2]), "+f"(d[3])
                 : "r"(a0), "r"(a1), "r"(a2), "r"(a3), "r"(b0), "r"(b1));
}

// ================= mask format detection =================
__global__ void k_detect_mask(const unsigned int* __restrict__ m) {
    __shared__ int found;
    if (threadIdx.x == 0) found = 0;
    __syncthreads();
    unsigned v = m[threadIdx.x];
    if (v > 1u) atomicOr(&found, 1);
    __syncthreads();
    if (threadIdx.x == 0) g_mask_is_byte = found;
}
__device__ __forceinline__ int read_mask(const void* p, int i) {
    if (g_mask_is_byte) return ((const unsigned char*)p)[i] != 0;
    return ((const int*)p)[i] != 0;
}

// ================= token_reps + positional encoding =================
__global__ void k_addpe(const float* __restrict__ tok) {
    int idx = blockIdx.x * 256 + threadIdx.x;
    int c = idx & 255;
    int s = (idx >> 8) & (S_ - 1);
    double div = exp((double)(c & ~1) * (-9.210340371976184 / 256.0));
    double arg = (double)s * div;
    float pe = (c & 1) ? (float)cos(arg) : (float)sin(arg);
    g_TR[idx] = tok[idx] + pe;
}

// ================= precompute: qk (scaled), output bias =================
__global__ void k_precompute(const float* __restrict__ dq, const float* __restrict__ wq,
                             const float* __restrict__ wk, const float* __restrict__ bqkv,
                             const float* __restrict__ wo, const float* __restrict__ bo) {
    __shared__ float qs[H_];
    int t = threadIdx.x;
    float s = bqkv[t];
    for (int c = 0; c < H_; c++) s += dq[c] * wq[t*H_ + c];
    qs[t] = s;
    __syncthreads();
    #pragma unroll
    for (int h = 0; h < NH_; h++) {
        float acc = 0.f;
        for (int d = 0; d < DH_; d++) acc += qs[h*DH_ + d] * wk[(h*DH_ + d)*H_ + t];
        g_QK[h*H_ + t] = 0.125f * acc;
    }
    float bacc = bo[t] + dq[t];
    for (int i = 0; i < H_; i++) bacc += bqkv[2*H_ + i] * wo[t*H_ + i];
    g_BO[t] = bacc;
}

// ================= fused prep: vtok | ltok | weight splits ==================
// blocks [0,256):    V_tok (8 tokens/block, float4 weights, unrolled)
// blocks [256,512):  L_tok (8 tokens/block, warp each)
// blocks [512,768):  esplit wo
// blocks [768,1792): tsplit w1 ([256][1024] -> [1024][256])
// blocks [1792,2816): tsplit w2 ([1024][256] -> [256][1024])
__global__ __launch_bounds__(256) void k_prep(const float* __restrict__ wv,
                                              const float* __restrict__ wo,
                                              const float* __restrict__ w1,
                                              const float* __restrict__ w2) {
    int bid = blockIdx.x;
    int tid = threadIdx.x;
    if (bid < 256) {
        // ---- vtok ----
        __shared__ float xs[8][H_];
        int t0 = bid * 8;
        #pragma unroll
        for (int r = 0; r < 8; r++) xs[r][tid] = g_TR[(t0 + r)*H_ + tid];
        __syncthreads();
        float acc[8] = {0,0,0,0,0,0,0,0};
        const float4* wr = (const float4*)(wv + (size_t)tid*H_);
        #pragma unroll 8
        for (int k4 = 0; k4 < H_/4; k4++) {
            float4 w = wr[k4];
            int k = k4 << 2;
            #pragma unroll
            for (int r = 0; r < 8; r++)
                acc[r] += xs[r][k]*w.x + xs[r][k+1]*w.y + xs[r][k+2]*w.z + xs[r][k+3]*w.w;
        }
        #pragma unroll
        for (int r = 0; r < 8; r++) g_Vtok[(t0 + r)*H_ + tid] = acc[r];
    } else if (bid < 512) {
        // ---- ltok ----
        int tok = (bid - 256) * 8 + (tid >> 5);
        int lane = tid & 31;
        const float* tr = g_TR + (size_t)tok*H_;
        float ax = 0.f, ay = 0.f, az = 0.f, aw = 0.f;
        #pragma unroll
        for (int i = 0; i < 8; i++) {
            int c = lane + 32*i;
            float x = tr[c];
            ax += x * g_QK[0*H_ + c];
            ay += x * g_QK[1*H_ + c];
            az += x * g_QK[2*H_ + c];
            aw += x * g_QK[3*H_ + c];
        }
        #pragma unroll
        for (int o = 16; o; o >>= 1) {
            ax += __shfl_xor_sync(0xFFFFFFFFu, ax, o);
            ay += __shfl_xor_sync(0xFFFFFFFFu, ay, o);
            az += __shfl_xor_sync(0xFFFFFFFFu, az, o);
            aw += __shfl_xor_sync(0xFFFFFFFFu, aw, o);
        }
        if (lane == 0) g_Ltok[tok] = make_float4(ax, ay, az, aw);
    } else if (bid < 768) {
        // ---- esplit wo ----
        int o = (bid - 512) * 256 + tid;
        __nv_bfloat16 hh, ll; split_bf16(wo[o], hh, ll);
        g_WOh[o] = hh; g_WOl[o] = ll;
    } else if (bid < 1792) {
        // ---- tsplit w1: o = n*256 + k, reads w1[k*1024 + n] ----
        int o = (bid - 768) * 256 + tid;
        int n = o >> 8, k = o & 255;
        __nv_bfloat16 hh, ll; split_bf16(w1[(size_t)k*FF_ + n], hh, ll);
        g_W1Th[o] = hh; g_W1Tl[o] = ll;
    } else {
        // ---- tsplit w2: o = n*1024 + k, reads w2[k*256 + n] ----
        int o = (bid - 1792) * 256 + tid;
        int n = o >> 10, k = o & 1023;
        __nv_bfloat16 hh, ll; split_bf16(w2[(size_t)k*H_ + n], hh, ll);
        g_W2Th[o] = hh; g_W2Tl[o] = ll;
    }
}

// ================= span kernel: one warp per span ============================
__global__ __launch_bounds__(256) void k_span(const int* __restrict__ span_ids,
                                              const void* __restrict__ maskp) {
    int sp = blockIdx.x * 8 + (threadIdx.x >> 5);
    int lane = threadIdx.x & 31;
    int start = span_ids[2*sp];
    int end   = span_ids[2*sp + 1];
    int len   = read_mask(maskp, sp) ? (end - start) : 0;
    int boff  = (sp >> 13) * S_;              // batch token offset

    int w = lane & 15;
    int gt = boff + min(max(start + w, 0), S_ - 1);
    bool valid = (w < len);

    float4 L = valid ? g_Ltok[gt] : make_float4(NEGV, NEGV, NEGV, NEGV);
    float mx = L.x, my = L.y, mz = L.z, mw = L.w;
    #pragma unroll
    for (int o = 8; o; o >>= 1) {
        mx = fmaxf(mx, __shfl_xor_sync(0xFFFFFFFFu, mx, o, 16));
        my = fmaxf(my, __shfl_xor_sync(0xFFFFFFFFu, my, o, 16));
        mz = fmaxf(mz, __shfl_xor_sync(0xFFFFFFFFu, mz, o, 16));
        mw = fmaxf(mw, __shfl_xor_sync(0xFFFFFFFFu, mw, o, 16));
    }
    float ex = valid ? expf(L.x - mx) : 0.f;
    float ey = valid ? expf(L.y - my) : 0.f;
    float ez = valid ? expf(L.z - mz) : 0.f;
    float ew = valid ? expf(L.w - mw) : 0.f;
    float sx = ex, sy = ey, sz = ez, sw = ew;
    #pragma unroll
    for (int o = 8; o; o >>= 1) {
        sx += __shfl_xor_sync(0xFFFFFFFFu, sx, o, 16);
        sy += __shfl_xor_sync(0xFFFFFFFFu, sy, o, 16);
        sz += __shfl_xor_sync(0xFFFFFFFFu, sz, o, 16);
        sw += __shfl_xor_sync(0xFFFFFFFFu, sw, o, 16);
    }
    // invalid lanes (w >= len) have e* = 0 -> attn weight 0; len==0 handled below
    float a0 = len ? ex / sx : 0.f;
    float a1 = len ? ey / sy : 0.f;
    float a2 = len ? ez / sz : 0.f;
    float a3 = len ? ew / sw : 0.f;

    // pooling, fully unrolled: weights are 0 beyond len, addresses are clamped-valid
    int hsel = lane >> 4;
    float acc0[4] = {0,0,0,0}, acc1[4] = {0,0,0,0};
    #pragma unroll
    for (int ww = 0; ww < MAXW; ww++) {
        int tw  = __shfl_sync(0xFFFFFFFFu, gt, ww);
        float b0 = __shfl_sync(0xFFFFFFFFu, a0, ww);
        float b1 = __shfl_sync(0xFFFFFFFFu, a1, ww);
        float b2 = __shfl_sync(0xFFFFFFFFu, a2, ww);
        float b3 = __shfl_sync(0xFFFFFFFFu, a3, ww);
        float s0 = hsel ? b1 : b0;
        float s1 = hsel ? b3 : b2;
        float4 v0 = *(const float4*)(g_Vtok + (size_t)tw*H_ + 4*lane);
        float4 v1 = *(const float4*)(g_Vtok + (size_t)tw*H_ + 128 + 4*lane);
        acc0[0] += s0*v0.x; acc0[1] += s0*v0.y; acc0[2] += s0*v0.z; acc0[3] += s0*v0.w;
        acc1[0] += s1*v1.x; acc1[1] += s1*v1.y; acc1[2] += s1*v1.z; acc1[3] += s1*v1.w;
    }
    union { __nv_bfloat16 b[4]; uint2 u; } H0, L0, H1, L1;
    #pragma unroll
    for (int e = 0; e < 4; e++) {
        split_bf16(acc0[e], H0.b[e], L0.b[e]);
        split_bf16(acc1[e], H1.b[e], L1.b[e]);
    }
    size_t base = (size_t)sp*H_ + 4*lane;
    *(uint2*)(g_Ctxh + base)       = H0.u;
    *(uint2*)(g_Ctxl + base)       = L0.u;
    *(uint2*)(g_Ctxh + base + 128) = H1.u;
    *(uint2*)(g_Ctxl + base + 128) = L1.u;
}

// ================= mma.sync bf16 GEMM, 3-term compensated ====================
#define PADK     40
#define MATSZ    (128*PADK)
#define STAGEB   (4*MATSZ*2)
#define NBUF     4
#define GSMEM_BYTES (NBUF*STAGEB)     // 163840

__device__ __forceinline__ void stage_load(uint32_t sbase, int buf,
        const __nv_bfloat16* __restrict__ Ah, const __nv_bfloat16* __restrict__ Al,
        const __nv_bfloat16* __restrict__ Bh, const __nv_bfloat16* __restrict__ Bl,
        int row0, int col0, int K, int kb, int tid) {
    uint32_t sb = sbase + buf*STAGEB;
    const __nv_bfloat16* P[4] = {Ah, Al, Bh, Bl};
    #pragma unroll
    for (int m = 0; m < 4; m++) {
        int r0 = (m < 2) ? row0 : col0;
        const __nv_bfloat16* p = P[m];
        #pragma unroll
        for (int half = 0; half < 2; half++) {
            int idx = tid + (half << 8);
            int row = idx >> 2, kc = idx & 3;
            cp16(sb + m*(MATSZ*2) + row*(PADK*2) + kc*16,
                 p + (size_t)(r0 + row)*K + kb + kc*8);
        }
    }
    CP_COMMIT();
}

template<int EPI>
__global__ __launch_bounds__(256)
void k_gemm(const __nv_bfloat16* __restrict__ Ah, const __nv_bfloat16* __restrict__ Al,
            const __nv_bfloat16* __restrict__ Bh, const __nv_bfloat16* __restrict__ Bl,
            const float* __restrict__ bias, float* __restrict__ C,
            __nv_bfloat16* __restrict__ Oh, __nv_bfloat16* __restrict__ Ol,
            const __nv_bfloat16* __restrict__ Rh, const __nv_bfloat16* __restrict__ Rl,
            int K, int N) {
    extern __shared__ __nv_bfloat16 smem[];
    uint32_t sbase = smem_u32(smem);
    const int tid = threadIdx.x, wid = tid >> 5, lane = tid & 31;
    const int row0 = blockIdx.y * 128, col0 = blockIdx.x * 128;
    const int wm = (wid >> 2) * 64;
    const int wn = (wid & 3) * 32;
    const int NSTG = K >> 5;

    const uint32_t aoff = ((lane & 15) * PADK + ((lane >> 4) << 3)) * 2;
    const uint32_t boff = (((((lane >> 4) << 3) + (lane & 7)) * PADK) + (((lane >> 3) & 1) << 3)) * 2;

    float acc[4][4][4];
    #pragma unroll
    for (int mi = 0; mi < 4; mi++)
        #pragma unroll
        for (int ni = 0; ni < 4; ni++)
            #pragma unroll
            for (int e = 0; e < 4; e++) acc[mi][ni][e] = 0.f;

    stage_load(sbase, 0, Ah, Al, Bh, Bl, row0, col0, K, 0,  tid);
    stage_load(sbase, 1, Ah, Al, Bh, Bl, row0, col0, K, 32, tid);
    stage_load(sbase, 2, Ah, Al, Bh, Bl, row0, col0, K, 64, tid);

    for (int s = 0; s < NSTG; s++) {
        CP_WAIT(2);
        __syncthreads();
        uint32_t sb = sbase + (s & 3)*STAGEB;
        uint32_t sAh = sb,                sAl = sb + MATSZ*2;
        uint32_t sBh = sb + 2*MATSZ*2,    sBl = sb + 3*MATSZ*2;

        #pragma unroll
        for (int kk = 0; kk < 2; kk++) {
            uint32_t kby = kk * 32;
            uint32_t a[4][4], bh[4][2], bl[4][2];
            #pragma unroll
            for (int mi = 0; mi < 4; mi++)
                ldsm4(a[mi][0], a[mi][1], a[mi][2], a[mi][3],
                      sAh + aoff + (wm + mi*16)*(PADK*2) + kby);
            #pragma unroll
            for (int nj = 0; nj < 2; nj++)
                ldsm4(bh[2*nj][0], bh[2*nj][1], bh[2*nj+1][0], bh[2*nj+1][1],
                      sBh + boff + (wn + nj*16)*(PADK*2) + kby);
            #pragma unroll
            for (int mi = 0; mi < 4; mi++)
                #pragma unroll
                for (int ni = 0; ni < 4; ni++)
                    mma16816(acc[mi][ni], a[mi][0], a[mi][1], a[mi][2], a[mi][3],
                             bh[ni][0], bh[ni][1]);
            #pragma unroll
            for (int nj = 0; nj < 2; nj++)
                ldsm4(bl[2*nj][0], bl[2*nj][1], bl[2*nj+1][0], bl[2*nj+1][1],
                      sBl + boff + (wn + nj*16)*(PADK*2) + kby);
            #pragma unroll
            for (int mi = 0; mi < 4; mi++)
                #pragma unroll
                for (int ni = 0; ni < 4; ni++)
                    mma16816(acc[mi][ni], a[mi][0], a[mi][1], a[mi][2], a[mi][3],
                             bl[ni][0], bl[ni][1]);
            #pragma unroll
            for (int mi = 0; mi < 4; mi++)
                ldsm4(a[mi][0], a[mi][1], a[mi][2], a[mi][3],
                      sAl + aoff + (wm + mi*16)*(PADK*2) + kby);
            #pragma unroll
            for (int mi = 0; mi < 4; mi++)
                #pragma unroll
                for (int ni = 0; ni < 4; ni++)
                    mma16816(acc[mi][ni], a[mi][0], a[mi][1], a[mi][2], a[mi][3],
                             bh[ni][0], bh[ni][1]);
        }
        int nx = s + 3;
        if (nx < NSTG) stage_load(sbase, nx & 3, Ah, Al, Bh, Bl, row0, col0, K, nx << 5, tid);
        else           CP_COMMIT();
    }

    // ---- epilogue ----
    #pragma unroll
    for (int mi = 0; mi < 4; mi++) {
        #pragma unroll
        for (int ni = 0; ni < 4; ni++) {
            int gr0 = row0 + wm + mi*16 + (lane >> 2);
            int gc  = col0 + wn + ni*8 + ((lane & 3) << 1);
            float b0 = bias[gc], b1 = bias[gc + 1];
            float v00 = acc[mi][ni][0] + b0, v01 = acc[mi][ni][1] + b1;
            float v10 = acc[mi][ni][2] + b0, v11 = acc[mi][ni][3] + b1;
            if (EPI == 0) {
                *(float2*)(C + (size_t)gr0*N + gc)       = make_float2(v00, v01);
                *(float2*)(C + (size_t)(gr0+8)*N + gc)   = make_float2(v10, v11);
            } else if (EPI == 1) {
                union { __nv_bfloat16 b[2]; uint32_t u; } h0, l0, h1, l1;
                float w00 = fmaxf(v00, 0.f), w01 = fmaxf(v01, 0.f);
                float w10 = fmaxf(v10, 0.f), w11 = fmaxf(v11, 0.f);
                split_bf16(w00, h0.b[0], l0.b[0]); split_bf16(w01, h0.b[1], l0.b[1]);
                split_bf16(w10, h1.b[0], l1.b[0]); split_bf16(w11, h1.b[1], l1.b[1]);
                *(uint32_t*)(Oh + (size_t)gr0*N + gc)     = h0.u;
                *(uint32_t*)(Ol + (size_t)gr0*N + gc)     = l0.u;
                *(uint32_t*)(Oh + (size_t)(gr0+8)*N + gc) = h1.u;
                *(uint32_t*)(Ol + (size_t)(gr0+8)*N + gc) = l1.u;
            } else {
                union { __nv_bfloat16 b[2]; uint32_t u; } rh0, rl0, rh1, rl1;
                rh0.u = *(const uint32_t*)(Rh + (size_t)gr0*N + gc);
                rl0.u = *(const uint32_t*)(Rl + (size_t)gr0*N + gc);
                rh1.u = *(const uint32_t*)(Rh + (size_t)(gr0+8)*N + gc);
                rl1.u = *(const uint32_t*)(Rl + (size_t)(gr0+8)*N + gc);
                v00 += __bfloat162float(rh0.b[0]) + __bfloat162float(rl0.b[0]);
                v01 += __bfloat162float(rh0.b[1]) + __bfloat162float(rl0.b[1]);
                v10 += __bfloat162float(rh1.b[0]) + __bfloat162float(rl1.b[0]);
                v11 += __bfloat162float(rh1.b[1]) + __bfloat162float(rl1.b[1]);
                *(float2*)(C + (size_t)gr0*N + gc)       = make_float2(v00, v01);
                *(float2*)(C + (size_t)(gr0+8)*N + gc)   = make_float2(v10, v11);
            }
        }
    }
}

// ================= LayerNorm variants =================
__global__ __launch_bounds__(256) void k_ln_bf16(const float* __restrict__ X,
        __nv_bfloat16* __restrict__ Yh, __nv_bfloat16* __restrict__ Yl,
        const float* __restrict__ g, const float* __restrict__ bb) {
    int gw = (blockIdx.x * 256 + threadIdx.x) >> 5;
    int lane = threadIdx.x & 31;
    const float* x = X + (size_t)gw * H_;
    float v[8]; float s = 0.f;
    #pragma unroll
    for (int i = 0; i < 8; i++) { v[i] = x[lane + 32*i]; s += v[i]; }
    #pragma unroll
    for (int o = 16; o; o >>= 1) s += __shfl_xor_sync(0xFFFFFFFFu, s, o);
    float mean = s * (1.f/H_);
    float sv = 0.f;
    #pragma unroll
    for (int i = 0; i < 8; i++) { float d = v[i] - mean; sv += d*d; }
    #pragma unroll
    for (int o = 16; o; o >>= 1) sv += __shfl_xor_sync(0xFFFFFFFFu, sv, o);
    float inv = rsqrtf(sv * (1.f/H_) + 1e-5f);
    #pragma unroll
    for (int i = 0; i < 8; i++) {
        int c = lane + 32*i;
        float yv = (v[i] - mean) * inv * g[c] + bb[c];
        __nv_bfloat16 hh, ll; split_bf16(yv, hh, ll);
        Yh[(size_t)gw*H_ + c] = hh;
        Yl[(size_t)gw*H_ + c] = ll;
    }
}

__global__ __launch_bounds__(256) void k_ln_final(const float* __restrict__ X, float* __restrict__ Yo,
        const float* __restrict__ g, const float* __restrict__ bb, const void* __restrict__ maskp) {
    int gw = (blockIdx.x * 256 + threadIdx.x) >> 5;
    int lane = threadIdx.x & 31;
    const float* x = X + (size_t)gw * H_;
    float v[8]; float s = 0.f;
    #pragma unroll
    for (int i = 0; i < 8; i++) { v[i] = x[lane + 32*i]; s += v[i]; }
    #pragma unroll
    for (int o = 16; o; o >>= 1) s += __shfl_xor_sync(0xFFFFFFFFu, s, o);
    float mean = s * (1.f/H_);
    float sv = 0.f;
    #pragma unroll
    for (int i = 0; i < 8; i++) { float d = v[i] - mean; sv += d*d; }
    #pragma unroll
    for (int o = 16; o; o >>= 1) sv += __shfl_xor_sync(0xFFFFFFFFu, sv, o);
    float inv = rsqrtf(sv * (1.f/H_) + 1e-5f);
    float mf = read_mask(maskp, gw) ? 1.f : 0.f;
    float* y = Yo + (size_t)gw * H_;
    #pragma unroll
    for (int i = 0; i < 8; i++) {
        int c = lane + 32*i;
        y[c] = ((v[i] - mean) * inv * g[c] + bb[c]) * mf;
    }
}

// ================= launch =================
extern "C" void kernel_launch(void* const* d_in, const int* in_sizes, int n_in,
                              void* d_out, int out_size) {
    const float* tok   = (const float*)d_in[0];
    const int*   sids  = (const int*)  d_in[1];
    const void*  masks =               d_in[2];
    const float* dq    = (const float*)d_in[4];
    const float* wq    = (const float*)d_in[5];
    const float* wk    = (const float*)d_in[6];
    const float* wv    = (const float*)d_in[7];
    const float* bqkv  = (const float*)d_in[8];
    const float* wo    = (const float*)d_in[9];
    const float* bo    = (const float*)d_in[10];
    const float* lng   = (const float*)d_in[11];
    const float* lnb   = (const float*)d_in[12];
    const float* w1    = (const float*)d_in[13];
    const float* b1    = (const float*)d_in[14];
    const float* w2    = (const float*)d_in[15];
    const float* b2    = (const float*)d_in[16];
    float* out = (float*)d_out;

    float *T1, *BO;
    __nv_bfloat16 *Ch, *Cl, *Yh, *Yl, *Fh, *Fl, *WOh, *WOl, *W1Th, *W1Tl, *W2Th, *W2Tl;
    cudaGetSymbolAddress((void**)&T1,  g_T1);
    cudaGetSymbolAddress((void**)&BO,  g_BO);
    cudaGetSymbolAddress((void**)&Ch,  g_Ctxh);
    cudaGetSymbolAddress((void**)&Cl,  g_Ctxl);
    cudaGetSymbolAddress((void**)&Yh,  g_Yh);
    cudaGetSymbolAddress((void**)&Yl,  g_Yl);
    cudaGetSymbolAddress((void**)&Fh,  g_Fh);
    cudaGetSymbolAddress((void**)&Fl,  g_Fl);
    cudaGetSymbolAddress((void**)&WOh, g_WOh);
    cudaGetSymbolAddress((void**)&WOl, g_WOl);
    cudaGetSymbolAddress((void**)&W1Th, g_W1Th);
    cudaGetSymbolAddress((void**)&W1Tl, g_W1Tl);
    cudaGetSymbolAddress((void**)&W2Th, g_W2Th);
    cudaGetSymbolAddress((void**)&W2Tl, g_W2Tl);

    cudaFuncSetAttribute(k_gemm<0>, cudaFuncAttributeMaxDynamicSharedMemorySize, GSMEM_BYTES);
    cudaFuncSetAttribute(k_gemm<1>, cudaFuncAttributeMaxDynamicSharedMemorySize, GSMEM_BYTES);
    cudaFuncSetAttribute(k_gemm<2>, cudaFuncAttributeMaxDynamicSharedMemorySize, GSMEM_BYTES);

    k_detect_mask<<<1, 256>>>((const unsigned int*)masks);
    k_addpe<<<(B_*S_*H_)/256, 256>>>(tok);
    k_precompute<<<1, 256>>>(dq, wq, wk, bqkv, wo, bo);
    k_prep<<<2816, 256>>>(wv, wo, w1, w2);
    k_span<<<NSPAN/8, 256>>>(sids, masks);

    // GEMM1': T1 = Ctx(32768x256) @ WO^T (N=256) + BO
    k_gemm<0><<<dim3(2, NSPAN/128), 256, GSMEM_BYTES>>>(Ch, Cl, WOh, WOl, BO, T1,
                                                        nullptr, nullptr, nullptr, nullptr, H_, H_);
    // Y = LN(T1) -> bf16 hi/lo
    k_ln_bf16<<<NSPAN/8, 256>>>(T1, Yh, Yl, lng, lnb);
    // GEMM2: F = relu(Y @ W1T^T (N=1024) + b1) -> bf16 hi/lo
    k_gemm<1><<<dim3(8, NSPAN/128), 256, GSMEM_BYTES>>>(Yh, Yl, W1Th, W1Tl, b1, nullptr,
                                                        Fh, Fl, nullptr, nullptr, H_, FF_);
    // GEMM3: T1 = F @ W2T^T (N=256) + b2 + Y
    k_gemm<2><<<dim3(2, NSPAN/128), 256, GSMEM_BYTES>>>(Fh, Fl, W2Th, W2Tl, b2, T1,
                                                        nullptr, nullptr, Yh, Yl, FF_, H_);
    // out = LN(T1) * mask
    k_ln_final<<<NSPAN/8, 256>>>(T1, out, lng, lnb, masks);
}

// round 10
// speedup vs baseline: 1.0666x; 1.0666x over previous
#include <cuda_runtime.h>
#include <cuda_bf16.h>
#include <cstdint>
#include <math.h>

// ================= problem constants =================
#define B_    4
#define S_    512
#define NS_   8192
#define MAXW  16
#define H_    256
#define NH_   4
#define DH_   64
#define FF_   1024
#define NSPAN (B_*NS_)          // 32768
#define NEGV  (-1000000000.0f)

// ================= device scratch =================
__device__ float g_TR[B_*S_*H_];
__device__ float g_QK[NH_*H_];
__device__ float g_BO[H_];
__device__ float g_Vtok[B_*S_*H_];
__device__ float4 g_Ltok[B_*S_];
__device__ float g_T1[(size_t)NSPAN*H_];
__device__ __nv_bfloat16 g_Ctxh[(size_t)NSPAN*H_];
__device__ __nv_bfloat16 g_Ctxl[(size_t)NSPAN*H_];
__device__ __nv_bfloat16 g_Yh[(size_t)NSPAN*H_];
__device__ __nv_bfloat16 g_Yl[(size_t)NSPAN*H_];
__device__ __nv_bfloat16 g_Fh[(size_t)NSPAN*FF_];
__device__ __nv_bfloat16 g_Fl[(size_t)NSPAN*FF_];
__device__ __nv_bfloat16 g_WOh[H_*H_];           // w_o split, [N][K] natural
__device__ __nv_bfloat16 g_WOl[H_*H_];
__device__ __nv_bfloat16 g_W1h[H_*FF_];          // w1 split, K-major [256][1024]
__device__ __nv_bfloat16 g_W1l[H_*FF_];
__device__ __nv_bfloat16 g_W2h[FF_*H_];          // w2 split, K-major [1024][256]
__device__ __nv_bfloat16 g_W2l[FF_*H_];
__device__ int g_mask_is_byte;

__device__ __forceinline__ void split_bf16(float x, __nv_bfloat16& h, __nv_bfloat16& l) {
    h = __float2bfloat16(x);
    l = __float2bfloat16(x - __bfloat162float(h));
}

// ================= small PTX helpers =================
__device__ __forceinline__ uint32_t smem_u32(const void* p) {
    uint32_t a;
    asm("{ .reg .u64 t; cvta.to.shared.u64 t, %1; cvt.u32.u64 %0, t; }" : "=r"(a) : "l"(p));
    return a;
}
__device__ __forceinline__ void cp16(uint32_t s, const void* g) {
    asm volatile("cp.async.cg.shared.global [%0], [%1], 16;" :: "r"(s), "l"(g));
}
#define CP_COMMIT() asm volatile("cp.async.commit_group;" ::: "memory")
#define CP_WAIT(n)  asm volatile("cp.async.wait_group %0;" :: "n"(n) : "memory")

__device__ __forceinline__ void ldsm4(uint32_t& r0, uint32_t& r1, uint32_t& r2, uint32_t& r3, uint32_t a) {
    asm volatile("ldmatrix.sync.aligned.m8n8.x4.shared.b16 {%0,%1,%2,%3}, [%4];"
                 : "=r"(r0), "=r"(r1), "=r"(r2), "=r"(r3) : "r"(a));
}
__device__ __forceinline__ void ldsm4t(uint32_t& r0, uint32_t& r1, uint32_t& r2, uint32_t& r3, uint32_t a) {
    asm volatile("ldmatrix.sync.aligned.m8n8.x4.trans.shared.b16 {%0,%1,%2,%3}, [%4];"
                 : "=r"(r0), "=r"(r1), "=r"(r2), "=r"(r3) : "r"(a));
}
__device__ __forceinline__ void mma16816(float* d, uint32_t a0, uint32_t a1, uint32_t a2, uint32_t a3,
                                         uint32_t b0, uint32_t b1) {
    asm volatile("mma.sync.aligned.m16n8k16.row.col.f32.bf16.bf16.f32 "
                 "{%0,%1,%2,%3}, {%4,%5,%6,%7}, {%8,%9}, {%0,%1,%2,%3};"
                 : "+f"(d[0]), "+f"(d[1]), "+f"(d[2]), "+f"(d[3])
                 : "r"(a0), "r"(a1), "r"(a2), "r"(a3), "r"(b0), "r"(b1));
}

__device__ __forceinline__ int read_mask(const void* p, int i) {
    if (g_mask_is_byte) return ((const unsigned char*)p)[i] != 0;
    return ((const int*)p)[i] != 0;
}

// ================= fused init: detect_mask | precompute | addpe ==============
// block 0: precompute (qk, BO); block 1: mask detect; blocks [2,2050): addpe
__global__ __launch_bounds__(256) void k_init(const float* __restrict__ tok,
        const unsigned int* __restrict__ m,
        const float* __restrict__ dq, const float* __restrict__ wq,
        const float* __restrict__ wk, const float* __restrict__ bqkv,
        const float* __restrict__ wo, const float* __restrict__ bo) {
    int bid = blockIdx.x;
    int t = threadIdx.x;
    if (bid == 0) {
        __shared__ float qs[H_];
        float s = bqkv[t];
        for (int c = 0; c < H_; c++) s += dq[c] * wq[t*H_ + c];
        qs[t] = s;
        __syncthreads();
        #pragma unroll
        for (int h = 0; h < NH_; h++) {
            float acc = 0.f;
            for (int d = 0; d < DH_; d++) acc += qs[h*DH_ + d] * wk[(h*DH_ + d)*H_ + t];
            g_QK[h*H_ + t] = 0.125f * acc;
        }
        float bacc = bo[t] + dq[t];
        for (int i = 0; i < H_; i++) bacc += bqkv[2*H_ + i] * wo[t*H_ + i];
        g_BO[t] = bacc;
    } else if (bid == 1) {
        __shared__ int found;
        if (t == 0) found = 0;
        __syncthreads();
        unsigned v = m[t];
        if (v > 1u) atomicOr(&found, 1);
        __syncthreads();
        if (t == 0) g_mask_is_byte = found;
    } else {
        int idx = (bid - 2) * 256 + t;
        int c = idx & 255;
        int s = (idx >> 8) & (S_ - 1);
        double div = exp((double)(c & ~1) * (-9.210340371976184 / 256.0));
        double arg = (double)s * div;
        float pe = (c & 1) ? (float)cos(arg) : (float)sin(arg);
        g_TR[idx] = tok[idx] + pe;
    }
}

// ================= fused prep: vtok | ltok | coalesced weight splits ========
// [0,256) vtok; [256,512) ltok; [512,768) split wo; [768,1792) split w1; [1792,2816) split w2
__global__ __launch_bounds__(256) void k_prep(const float* __restrict__ wv,
                                              const float* __restrict__ wo,
                                              const float* __restrict__ w1,
                                              const float* __restrict__ w2) {
    int bid = blockIdx.x;
    int tid = threadIdx.x;
    if (bid < 256) {
        __shared__ float xs[8][H_];
        int t0 = bid * 8;
        #pragma unroll
        for (int r = 0; r < 8; r++) xs[r][tid] = g_TR[(t0 + r)*H_ + tid];
        __syncthreads();
        float acc[8] = {0,0,0,0,0,0,0,0};
        const float4* wr = (const float4*)(wv + (size_t)tid*H_);
        #pragma unroll 8
        for (int k4 = 0; k4 < H_/4; k4++) {
            float4 w = wr[k4];
            int k = k4 << 2;
            #pragma unroll
            for (int r = 0; r < 8; r++)
                acc[r] += xs[r][k]*w.x + xs[r][k+1]*w.y + xs[r][k+2]*w.z + xs[r][k+3]*w.w;
        }
        #pragma unroll
        for (int r = 0; r < 8; r++) g_Vtok[(t0 + r)*H_ + tid] = acc[r];
    } else if (bid < 512) {
        int tok = (bid - 256) * 8 + (tid >> 5);
        int lane = tid & 31;
        const float* tr = g_TR + (size_t)tok*H_;
        float ax = 0.f, ay = 0.f, az = 0.f, aw = 0.f;
        #pragma unroll
        for (int i = 0; i < 8; i++) {
            int c = lane + 32*i;
            float x = tr[c];
            ax += x * g_QK[0*H_ + c];
            ay += x * g_QK[1*H_ + c];
            az += x * g_QK[2*H_ + c];
            aw += x * g_QK[3*H_ + c];
        }
        #pragma unroll
        for (int o = 16; o; o >>= 1) {
            ax += __shfl_xor_sync(0xFFFFFFFFu, ax, o);
            ay += __shfl_xor_sync(0xFFFFFFFFu, ay, o);
            az += __shfl_xor_sync(0xFFFFFFFFu, az, o);
            aw += __shfl_xor_sync(0xFFFFFFFFu, aw, o);
        }
        if (lane == 0) g_Ltok[tok] = make_float4(ax, ay, az, aw);
    } else if (bid < 768) {
        int o = (bid - 512) * 256 + tid;
        __nv_bfloat16 hh, ll; split_bf16(wo[o], hh, ll);
        g_WOh[o] = hh; g_WOl[o] = ll;
    } else if (bid < 1792) {
        int o = (bid - 768) * 256 + tid;          // natural order, coalesced
        __nv_bfloat16 hh, ll; split_bf16(w1[o], hh, ll);
        g_W1h[o] = hh; g_W1l[o] = ll;
    } else {
        int o = (bid - 1792) * 256 + tid;
        __nv_bfloat16 hh, ll; split_bf16(w2[o], hh, ll);
        g_W2h[o] = hh; g_W2l[o] = ll;
    }
}

// ================= span kernel: one warp per span ============================
__global__ __launch_bounds__(256) void k_span(const int* __restrict__ span_ids,
                                              const void* __restrict__ maskp) {
    int sp = blockIdx.x * 8 + (threadIdx.x >> 5);
    int lane = threadIdx.x & 31;
    int start = span_ids[2*sp];
    int end   = span_ids[2*sp + 1];
    int len   = read_mask(maskp, sp) ? (end - start) : 0;
    int boff  = (sp >> 13) * S_;

    int w = lane & 15;
    int gt = boff + min(max(start + w, 0), S_ - 1);
    bool valid = (w < len);

    float4 L = valid ? g_Ltok[gt] : make_float4(NEGV, NEGV, NEGV, NEGV);
    float mx = L.x, my = L.y, mz = L.z, mw = L.w;
    #pragma unroll
    for (int o = 8; o; o >>= 1) {
        mx = fmaxf(mx, __shfl_xor_sync(0xFFFFFFFFu, mx, o, 16));
        my = fmaxf(my, __shfl_xor_sync(0xFFFFFFFFu, my, o, 16));
        mz = fmaxf(mz, __shfl_xor_sync(0xFFFFFFFFu, mz, o, 16));
        mw = fmaxf(mw, __shfl_xor_sync(0xFFFFFFFFu, mw, o, 16));
    }
    float ex = valid ? expf(L.x - mx) : 0.f;
    float ey = valid ? expf(L.y - my) : 0.f;
    float ez = valid ? expf(L.z - mz) : 0.f;
    float ew = valid ? expf(L.w - mw) : 0.f;
    float sx = ex, sy = ey, sz = ez, sw = ew;
    #pragma unroll
    for (int o = 8; o; o >>= 1) {
        sx += __shfl_xor_sync(0xFFFFFFFFu, sx, o, 16);
        sy += __shfl_xor_sync(0xFFFFFFFFu, sy, o, 16);
        sz += __shfl_xor_sync(0xFFFFFFFFu, sz, o, 16);
        sw += __shfl_xor_sync(0xFFFFFFFFu, sw, o, 16);
    }
    float a0 = len ? ex / sx : 0.f;
    float a1 = len ? ey / sy : 0.f;
    float a2 = len ? ez / sz : 0.f;
    float a3 = len ? ew / sw : 0.f;

    int hsel = lane >> 4;
    float acc0[4] = {0,0,0,0}, acc1[4] = {0,0,0,0};
    #pragma unroll
    for (int ww = 0; ww < MAXW; ww++) {
        int tw  = __shfl_sync(0xFFFFFFFFu, gt, ww);
        float b0 = __shfl_sync(0xFFFFFFFFu, a0, ww);
        float b1 = __shfl_sync(0xFFFFFFFFu, a1, ww);
        float b2 = __shfl_sync(0xFFFFFFFFu, a2, ww);
        float b3 = __shfl_sync(0xFFFFFFFFu, a3, ww);
        float s0 = hsel ? b1 : b0;
        float s1 = hsel ? b3 : b2;
        float4 v0 = *(const float4*)(g_Vtok + (size_t)tw*H_ + 4*lane);
        float4 v1 = *(const float4*)(g_Vtok + (size_t)tw*H_ + 128 + 4*lane);
        acc0[0] += s0*v0.x; acc0[1] += s0*v0.y; acc0[2] += s0*v0.z; acc0[3] += s0*v0.w;
        acc1[0] += s1*v1.x; acc1[1] += s1*v1.y; acc1[2] += s1*v1.z; acc1[3] += s1*v1.w;
    }
    union { __nv_bfloat16 b[4]; uint2 u; } H0, L0, H1, L1;
    #pragma unroll
    for (int e = 0; e < 4; e++) {
        split_bf16(acc0[e], H0.b[e], L0.b[e]);
        split_bf16(acc1[e], H1.b[e], L1.b[e]);
    }
    size_t base = (size_t)sp*H_ + 4*lane;
    *(uint2*)(g_Ctxh + base)       = H0.u;
    *(uint2*)(g_Ctxl + base)       = L0.u;
    *(uint2*)(g_Ctxh + base + 128) = H1.u;
    *(uint2*)(g_Ctxl + base + 128) = L1.u;
}

// ================= mma.sync bf16 GEMM, 3-term compensated ====================
// BT=0: B global [N][K] (smem [128n][40k]);  BT=1: B global [K][N] (smem [32k][136n], ldsm.trans)
#define PADK     40
#define PADN     136
#define MATSZ    (128*PADK)           // 5120 elems (A slot; B-trans uses <= this)
#define STAGEB   (4*MATSZ*2)          // 40960 B
#define NBUF     5
#define GSMEM_BYTES (NBUF*STAGEB)     // 204800

template<int BT>
__device__ __forceinline__ void stage_load(uint32_t sbase, int buf,
        const __nv_bfloat16* __restrict__ Ah, const __nv_bfloat16* __restrict__ Al,
        const __nv_bfloat16* __restrict__ Bh, const __nv_bfloat16* __restrict__ Bl,
        int row0, int col0, int K, int N, int kb, int tid) {
    uint32_t sb = sbase + buf*STAGEB;
    // A hi/lo: [128 rows][PADK]
    #pragma unroll
    for (int m = 0; m < 2; m++) {
        const __nv_bfloat16* p = m ? Al : Ah;
        #pragma unroll
        for (int half = 0; half < 2; half++) {
            int idx = tid + (half << 8);
            int row = idx >> 2, kc = idx & 3;
            cp16(sb + m*(MATSZ*2) + row*(PADK*2) + kc*16,
                 p + (size_t)(row0 + row)*K + kb + kc*8);
        }
    }
    // B hi/lo
    #pragma unroll
    for (int m = 0; m < 2; m++) {
        const __nv_bfloat16* p = m ? Bl : Bh;
        #pragma unroll
        for (int half = 0; half < 2; half++) {
            int idx = tid + (half << 8);
            if (BT == 0) {
                int row = idx >> 2, kc = idx & 3;
                cp16(sb + (2 + m)*(MATSZ*2) + row*(PADK*2) + kc*16,
                     p + (size_t)(col0 + row)*K + kb + kc*8);
            } else {
                int row = idx >> 4, nc = idx & 15;      // 32 k-rows x 16 chunks
                cp16(sb + (2 + m)*(MATSZ*2) + row*(PADN*2) + nc*16,
                     p + (size_t)(kb + row)*N + col0 + nc*8);
            }
        }
    }
    CP_COMMIT();
}

template<int EPI, int BT>
__global__ __launch_bounds__(256)
void k_gemm(const __nv_bfloat16* __restrict__ Ah, const __nv_bfloat16* __restrict__ Al,
            const __nv_bfloat16* __restrict__ Bh, const __nv_bfloat16* __restrict__ Bl,
            const float* __restrict__ bias, float* __restrict__ C,
            __nv_bfloat16* __restrict__ Oh, __nv_bfloat16* __restrict__ Ol,
            const __nv_bfloat16* __restrict__ Rh, const __nv_bfloat16* __restrict__ Rl,
            int K, int N) {
    extern __shared__ __nv_bfloat16 smem[];
    uint32_t sbase = smem_u32(smem);
    const int tid = threadIdx.x, wid = tid >> 5, lane = tid & 31;
    const int row0 = blockIdx.y * 128, col0 = blockIdx.x * 128;
    const int wm = (wid >> 2) * 64;
    const int wn = (wid & 3) * 32;
    const int NSTG = K >> 5;              // >= 8

    const uint32_t aoff  = ((lane & 15) * PADK + ((lane >> 4) << 3)) * 2;
    const uint32_t boff  = (((((lane >> 4) << 3) + (lane & 7)) * PADK) + (((lane >> 3) & 1) << 3)) * 2;
    const uint32_t btoff = ((lane & 15) * PADN + ((lane >> 4) << 3)) * 2;

    float acc[4][4][4];
    #pragma unroll
    for (int mi = 0; mi < 4; mi++)
        #pragma unroll
        for (int ni = 0; ni < 4; ni++)
            #pragma unroll
            for (int e = 0; e < 4; e++) acc[mi][ni][e] = 0.f;

    stage_load<BT>(sbase, 0, Ah, Al, Bh, Bl, row0, col0, K, N, 0,  tid);
    stage_load<BT>(sbase, 1, Ah, Al, Bh, Bl, row0, col0, K, N, 32, tid);
    stage_load<BT>(sbase, 2, Ah, Al, Bh, Bl, row0, col0, K, N, 64, tid);
    stage_load<BT>(sbase, 3, Ah, Al, Bh, Bl, row0, col0, K, N, 96, tid);

    for (int s = 0; s < NSTG; s++) {
        CP_WAIT(3);
        __syncthreads();
        uint32_t sb = sbase + (s % NBUF)*STAGEB;
        uint32_t sAh = sb,                sAl = sb + MATSZ*2;
        uint32_t sBh = sb + 2*MATSZ*2,    sBl = sb + 3*MATSZ*2;

        #pragma unroll
        for (int kk = 0; kk < 2; kk++) {
            uint32_t kby  = kk * 32;          // A: 16 elems * 2B
            uint32_t kbyt = kk * (16*PADN*2); // B-trans: 16 k-rows
            uint32_t a[4][4], bh[4][2], bl[4][2];
            #pragma unroll
            for (int mi = 0; mi < 4; mi++)
                ldsm4(a[mi][0], a[mi][1], a[mi][2], a[mi][3],
                      sAh + aoff + (wm + mi*16)*(PADK*2) + kby);
            #pragma unroll
            for (int nj = 0; nj < 2; nj++) {
                if (BT == 0)
                    ldsm4(bh[2*nj][0], bh[2*nj][1], bh[2*nj+1][0], bh[2*nj+1][1],
                          sBh + boff + (wn + nj*16)*(PADK*2) + kby);
                else
                    ldsm4t(bh[2*nj][0], bh[2*nj][1], bh[2*nj+1][0], bh[2*nj+1][1],
                           sBh + btoff + kbyt + (wn + nj*16)*2);
            }
            #pragma unroll
            for (int mi = 0; mi < 4; mi++)
                #pragma unroll
                for (int ni = 0; ni < 4; ni++)
                    mma16816(acc[mi][ni], a[mi][0], a[mi][1], a[mi][2], a[mi][3],
                             bh[ni][0], bh[ni][1]);
            #pragma unroll
            for (int nj = 0; nj < 2; nj++) {
                if (BT == 0)
                    ldsm4(bl[2*nj][0], bl[2*nj][1], bl[2*nj+1][0], bl[2*nj+1][1],
                          sBl + boff + (wn + nj*16)*(PADK*2) + kby);
                else
                    ldsm4t(bl[2*nj][0], bl[2*nj][1], bl[2*nj+1][0], bl[2*nj+1][1],
                           sBl + btoff + kbyt + (wn + nj*16)*2);
            }
            #pragma unroll
            for (int mi = 0; mi < 4; mi++)
                #pragma unroll
                for (int ni = 0; ni < 4; ni++)
                    mma16816(acc[mi][ni], a[mi][0], a[mi][1], a[mi][2], a[mi][3],
                             bl[ni][0], bl[ni][1]);
            #pragma unroll
            for (int mi = 0; mi < 4; mi++)
                ldsm4(a[mi][0], a[mi][1], a[mi][2], a[mi][3],
                      sAl + aoff + (wm + mi*16)*(PADK*2) + kby);
            #pragma unroll
            for (int mi = 0; mi < 4; mi++)
                #pragma unroll
                for (int ni = 0; ni < 4; ni++)
                    mma16816(acc[mi][ni], a[mi][0], a[mi][1], a[mi][2], a[mi][3],
                             bh[ni][0], bh[ni][1]);
        }
        int nx = s + 4;
        if (nx < NSTG) stage_load<BT>(sbase, nx % NBUF, Ah, Al, Bh, Bl, row0, col0, K, N, nx << 5, tid);
        else           CP_COMMIT();
    }

    // ---- epilogue ----
    #pragma unroll
    for (int mi = 0; mi < 4; mi++) {
        #pragma unroll
        for (int ni = 0; ni < 4; ni++) {
            int gr0 = row0 + wm + mi*16 + (lane >> 2);
            int gc  = col0 + wn + ni*8 + ((lane & 3) << 1);
            float b0 = bias[gc], b1 = bias[gc + 1];
            float v00 = acc[mi][ni][0] + b0, v01 = acc[mi][ni][1] + b1;
            float v10 = acc[mi][ni][2] + b0, v11 = acc[mi][ni][3] + b1;
            if (EPI == 0) {
                *(float2*)(C + (size_t)gr0*N + gc)       = make_float2(v00, v01);
                *(float2*)(C + (size_t)(gr0+8)*N + gc)   = make_float2(v10, v11);
            } else if (EPI == 1) {
                union { __nv_bfloat16 b[2]; uint32_t u; } h0, l0, h1, l1;
                float w00 = fmaxf(v00, 0.f), w01 = fmaxf(v01, 0.f);
                float w10 = fmaxf(v10, 0.f), w11 = fmaxf(v11, 0.f);
                split_bf16(w00, h0.b[0], l0.b[0]); split_bf16(w01, h0.b[1], l0.b[1]);
                split_bf16(w10, h1.b[0], l1.b[0]); split_bf16(w11, h1.b[1], l1.b[1]);
                *(uint32_t*)(Oh + (size_t)gr0*N + gc)     = h0.u;
                *(uint32_t*)(Ol + (size_t)gr0*N + gc)     = l0.u;
                *(uint32_t*)(Oh + (size_t)(gr0+8)*N + gc) = h1.u;
                *(uint32_t*)(Ol + (size_t)(gr0+8)*N + gc) = l1.u;
            } else {
                union { __nv_bfloat16 b[2]; uint32_t u; } rh0, rl0, rh1, rl1;
                rh0.u = *(const uint32_t*)(Rh + (size_t)gr0*N + gc);
                rl0.u = *(const uint32_t*)(Rl + (size_t)gr0*N + gc);
                rh1.u = *(const uint32_t*)(Rh + (size_t)(gr0+8)*N + gc);
                rl1.u = *(const uint32_t*)(Rl + (size_t)(gr0+8)*N + gc);
                v00 += __bfloat162float(rh0.b[0]) + __bfloat162float(rl0.b[0]);
                v01 += __bfloat162float(rh0.b[1]) + __bfloat162float(rl0.b[1]);
                v10 += __bfloat162float(rh1.b[0]) + __bfloat162float(rl1.b[0]);
                v11 += __bfloat162float(rh1.b[1]) + __bfloat162float(rl1.b[1]);
                *(float2*)(C + (size_t)gr0*N + gc)       = make_float2(v00, v01);
                *(float2*)(C + (size_t)(gr0+8)*N + gc)   = make_float2(v10, v11);
            }
        }
    }
}

// ================= LayerNorm variants =================
__global__ __launch_bounds__(256) void k_ln_bf16(const float* __restrict__ X,
        __nv_bfloat16* __restrict__ Yh, __nv_bfloat16* __restrict__ Yl,
        const float* __restrict__ g, const float* __restrict__ bb) {
    int gw = (blockIdx.x * 256 + threadIdx.x) >> 5;
    int lane = threadIdx.x & 31;
    const float* x = X + (size_t)gw * H_;
    float v[8]; float s = 0.f;
    #pragma unroll
    for (int i = 0; i < 8; i++) { v[i] = x[lane + 32*i]; s += v[i]; }
    #pragma unroll
    for (int o = 16; o; o >>= 1) s += __shfl_xor_sync(0xFFFFFFFFu, s, o);
    float mean = s * (1.f/H_);
    float sv = 0.f;
    #pragma unroll
    for (int i = 0; i < 8; i++) { float d = v[i] - mean; sv += d*d; }
    #pragma unroll
    for (int o = 16; o; o >>= 1) sv += __shfl_xor_sync(0xFFFFFFFFu, sv, o);
    float inv = rsqrtf(sv * (1.f/H_) + 1e-5f);
    #pragma unroll
    for (int i = 0; i < 8; i++) {
        int c = lane + 32*i;
        float yv = (v[i] - mean) * inv * g[c] + bb[c];
        __nv_bfloat16 hh, ll; split_bf16(yv, hh, ll);
        Yh[(size_t)gw*H_ + c] = hh;
        Yl[(size_t)gw*H_ + c] = ll;
    }
}

__global__ __launch_bounds__(256) void k_ln_final(const float* __restrict__ X, float* __restrict__ Yo,
        const float* __restrict__ g, const float* __restrict__ bb, const void* __restrict__ maskp) {
    int gw = (blockIdx.x * 256 + threadIdx.x) >> 5;
    int lane = threadIdx.x & 31;
    const float* x = X + (size_t)gw * H_;
    float v[8]; float s = 0.f;
    #pragma unroll
    for (int i = 0; i < 8; i++) { v[i] = x[lane + 32*i]; s += v[i]; }
    #pragma unroll
    for (int o = 16; o; o >>= 1) s += __shfl_xor_sync(0xFFFFFFFFu, s, o);
    float mean = s * (1.f/H_);
    float sv = 0.f;
    #pragma unroll
    for (int i = 0; i < 8; i++) { float d = v[i] - mean; sv += d*d; }
    #pragma unroll
    for (int o = 16; o; o >>= 1) sv += __shfl_xor_sync(0xFFFFFFFFu, sv, o);
    float inv = rsqrtf(sv * (1.f/H_) + 1e-5f);
    float mf = read_mask(maskp, gw) ? 1.f : 0.f;
    float* y = Yo + (size_t)gw * H_;
    #pragma unroll
    for (int i = 0; i < 8; i++) {
        int c = lane + 32*i;
        y[c] = ((v[i] - mean) * inv * g[c] + bb[c]) * mf;
    }
}

// ================= launch =================
extern "C" void kernel_launch(void* const* d_in, const int* in_sizes, int n_in,
                              void* d_out, int out_size) {
    const float* tok   = (const float*)d_in[0];
    const int*   sids  = (const int*)  d_in[1];
    const void*  masks =               d_in[2];
    const float* dq    = (const float*)d_in[4];
    const float* wq    = (const float*)d_in[5];
    const float* wk    = (const float*)d_in[6];
    const float* wv    = (const float*)d_in[7];
    const float* bqkv  = (const float*)d_in[8];
    const float* wo    = (const float*)d_in[9];
    const float* bo    = (const float*)d_in[10];
    const float* lng   = (const float*)d_in[11];
    const float* lnb   = (const float*)d_in[12];
    const float* w1    = (const float*)d_in[13];
    const float* b1    = (const float*)d_in[14];
    const float* w2    = (const float*)d_in[15];
    const float* b2    = (const float*)d_in[16];
    float* out = (float*)d_out;

    float *T1, *BO;
    __nv_bfloat16 *Ch, *Cl, *Yh, *Yl, *Fh, *Fl, *WOh, *WOl, *W1h, *W1l, *W2h, *W2l;
    cudaGetSymbolAddress((void**)&T1,  g_T1);
    cudaGetSymbolAddress((void**)&BO,  g_BO);
    cudaGetSymbolAddress((void**)&Ch,  g_Ctxh);
    cudaGetSymbolAddress((void**)&Cl,  g_Ctxl);
    cudaGetSymbolAddress((void**)&Yh,  g_Yh);
    cudaGetSymbolAddress((void**)&Yl,  g_Yl);
    cudaGetSymbolAddress((void**)&Fh,  g_Fh);
    cudaGetSymbolAddress((void**)&Fl,  g_Fl);
    cudaGetSymbolAddress((void**)&WOh, g_WOh);
    cudaGetSymbolAddress((void**)&WOl, g_WOl);
    cudaGetSymbolAddress((void**)&W1h, g_W1h);
    cudaGetSymbolAddress((void**)&W1l, g_W1l);
    cudaGetSymbolAddress((void**)&W2h, g_W2h);
    cudaGetSymbolAddress((void**)&W2l, g_W2l);

    cudaFuncSetAttribute(k_gemm<0,0>, cudaFuncAttributeMaxDynamicSharedMemorySize, GSMEM_BYTES);
    cudaFuncSetAttribute(k_gemm<1,1>, cudaFuncAttributeMaxDynamicSharedMemorySize, GSMEM_BYTES);
    cudaFuncSetAttribute(k_gemm<2,1>, cudaFuncAttributeMaxDynamicSharedMemorySize, GSMEM_BYTES);

    k_init<<<2050, 256>>>(tok, (const unsigned int*)masks, dq, wq, wk, bqkv, wo, bo);
    k_prep<<<2816, 256>>>(wv, wo, w1, w2);
    k_span<<<NSPAN/8, 256>>>(sids, masks);

    // GEMM1: T1 = Ctx(32768x256) @ WO^T (N=256) + BO        [B = [N][K], non-trans]
    k_gemm<0,0><<<dim3(2, NSPAN/128), 256, GSMEM_BYTES>>>(Ch, Cl, WOh, WOl, BO, T1,
                                                          nullptr, nullptr, nullptr, nullptr, H_, H_);
    // Y = LN(T1) -> bf16 hi/lo
    k_ln_bf16<<<NSPAN/8, 256>>>(T1, Yh, Yl, lng, lnb);
    // GEMM2: F = relu(Y @ w1 + b1) -> bf16 hi/lo            [B = w1 [K=256][N=1024], trans]
    k_gemm<1,1><<<dim3(8, NSPAN/128), 256, GSMEM_BYTES>>>(Yh, Yl, W1h, W1l, b1, nullptr,
                                                          Fh, Fl, nullptr, nullptr, H_, FF_);
    // GEMM3: T1 = F @ w2 + b2 + Y                           [B = w2 [K=1024][N=256], trans]
    k_gemm<2,1><<<dim3(2, NSPAN/128), 256, GSMEM_BYTES>>>(Fh, Fl, W2h, W2l, b2, T1,
                                                          nullptr, nullptr, Yh, Yl, FF_, H_);
    // out = LN(T1) * mask
    k_ln_final<<<NSPAN/8, 256>>>(T1, out, lng, lnb, masks);
}

// round 11
// speedup vs baseline: 1.0689x; 1.0021x over previous
#include <cuda_runtime.h>
#include <cuda_bf16.h>
#include <cstdint>
#include <math.h>

// ================= problem constants =================
#define B_    4
#define S_    512
#define NS_   8192
#define MAXW  16
#define H_    256
#define NH_   4
#define DH_   64
#define FF_   1024
#define NSPAN (B_*NS_)          // 32768
#define NEGV  (-1000000000.0f)

// ================= device scratch =================
__device__ float g_TR[B_*S_*H_];
__device__ float g_QK[NH_*H_];
__device__ float g_BO[H_];
__device__ float g_Vtok[B_*S_*H_];
__device__ float4 g_Ltok[B_*S_];
__device__ float g_T1[(size_t)NSPAN*H_];
__device__ __nv_bfloat16 g_Ctxh[(size_t)NSPAN*H_];
__device__ __nv_bfloat16 g_Ctxl[(size_t)NSPAN*H_];
__device__ __nv_bfloat16 g_Yh[(size_t)NSPAN*H_];
__device__ __nv_bfloat16 g_Yl[(size_t)NSPAN*H_];
__device__ __nv_bfloat16 g_Fh[(size_t)NSPAN*FF_];
__device__ __nv_bfloat16 g_Fl[(size_t)NSPAN*FF_];
__device__ __nv_bfloat16 g_WOh[H_*H_];           // w_o split, [N][K] natural
__device__ __nv_bfloat16 g_WOl[H_*H_];
__device__ __nv_bfloat16 g_W1h[H_*FF_];          // w1 split, K-major [256][1024]
__device__ __nv_bfloat16 g_W1l[H_*FF_];
__device__ __nv_bfloat16 g_W2h[FF_*H_];          // w2 split, K-major [1024][256]
__device__ __nv_bfloat16 g_W2l[FF_*H_];
__device__ int g_mask_is_byte;

__device__ __forceinline__ void split_bf16(float x, __nv_bfloat16& h, __nv_bfloat16& l) {
    h = __float2bfloat16(x);
    l = __float2bfloat16(x - __bfloat162float(h));
}

// ================= small PTX helpers =================
__device__ __forceinline__ uint32_t smem_u32(const void* p) {
    uint32_t a;
    asm("{ .reg .u64 t; cvta.to.shared.u64 t, %1; cvt.u32.u64 %0, t; }" : "=r"(a) : "l"(p));
    return a;
}
__device__ __forceinline__ void cp16(uint32_t s, const void* g) {
    asm volatile("cp.async.cg.shared.global [%0], [%1], 16;" :: "r"(s), "l"(g));
}
#define CP_COMMIT() asm volatile("cp.async.commit_group;" ::: "memory")
#define CP_WAIT(n)  asm volatile("cp.async.wait_group %0;" :: "n"(n) : "memory")

__device__ __forceinline__ void ldsm4(uint32_t& r0, uint32_t& r1, uint32_t& r2, uint32_t& r3, uint32_t a) {
    asm volatile("ldmatrix.sync.aligned.m8n8.x4.shared.b16 {%0,%1,%2,%3}, [%4];"
                 : "=r"(r0), "=r"(r1), "=r"(r2), "=r"(r3) : "r"(a));
}
__device__ __forceinline__ void ldsm4t(uint32_t& r0, uint32_t& r1, uint32_t& r2, uint32_t& r3, uint32_t a) {
    asm volatile("ldmatrix.sync.aligned.m8n8.x4.trans.shared.b16 {%0,%1,%2,%3}, [%4];"
                 : "=r"(r0), "=r"(r1), "=r"(r2), "=r"(r3) : "r"(a));
}
__device__ __forceinline__ void mma16816(float* d, uint32_t a0, uint32_t a1, uint32_t a2, uint32_t a3,
                                         uint32_t b0, uint32_t b1) {
    asm volatile("mma.sync.aligned.m16n8k16.row.col.f32.bf16.bf16.f32 "
                 "{%0,%1,%2,%3}, {%4,%5,%6,%7}, {%8,%9}, {%0,%1,%2,%3};"
                 : "+f"(d[0]), "+f"(d[1]), "+f"(d[2]), "+f"(d[3])
                 : "r"(a0), "r"(a1), "r"(a2), "r"(a3), "r"(b0), "r"(b1));
}

__device__ __forceinline__ int read_mask(const void* p, int i) {
    if (g_mask_is_byte) return ((const unsigned char*)p)[i] != 0;
    return ((const int*)p)[i] != 0;
}

// ================= fused init: detect_mask | precompute | addpe ==============
// block 0: precompute (qk, BO); block 1: mask detect; blocks [2,2050): addpe
__global__ __launch_bounds__(256) void k_init(const float* __restrict__ tok,
        const unsigned int* __restrict__ m,
        const float* __restrict__ dq, const float* __restrict__ wq,
        const float* __restrict__ wk, const float* __restrict__ bqkv,
        const float* __restrict__ wo, const float* __restrict__ bo) {
    int bid = blockIdx.x;
    int t = threadIdx.x;
    if (bid == 0) {
        __shared__ float qs[H_];
        float s = bqkv[t];
        for (int c = 0; c < H_; c++) s += dq[c] * wq[t*H_ + c];
        qs[t] = s;
        __syncthreads();
        #pragma unroll
        for (int h = 0; h < NH_; h++) {
            float acc = 0.f;
            for (int d = 0; d < DH_; d++) acc += qs[h*DH_ + d] * wk[(h*DH_ + d)*H_ + t];
            g_QK[h*H_ + t] = 0.125f * acc;
        }
        float bacc = bo[t] + dq[t];
        for (int i = 0; i < H_; i++) bacc += bqkv[2*H_ + i] * wo[t*H_ + i];
        g_BO[t] = bacc;
    } else if (bid == 1) {
        __shared__ int found;
        if (t == 0) found = 0;
        __syncthreads();
        unsigned v = m[t];
        if (v > 1u) atomicOr(&found, 1);
        __syncthreads();
        if (t == 0) g_mask_is_byte = found;
    } else {
        int idx = (bid - 2) * 256 + t;
        int c = idx & 255;
        int s = (idx >> 8) & (S_ - 1);
        double div = exp((double)(c & ~1) * (-9.210340371976184 / 256.0));
        double arg = (double)s * div;
        float pe = (c & 1) ? (float)cos(arg) : (float)sin(arg);
        g_TR[idx] = tok[idx] + pe;
    }
}

// ================= fused prep: vtok | ltok | coalesced weight splits ========
// [0,256) vtok; [256,512) ltok; [512,768) split wo; [768,1792) split w1; [1792,2816) split w2
__global__ __launch_bounds__(256) void k_prep(const float* __restrict__ wv,
                                              const float* __restrict__ wo,
                                              const float* __restrict__ w1,
                                              const float* __restrict__ w2) {
    int bid = blockIdx.x;
    int tid = threadIdx.x;
    if (bid < 256) {
        __shared__ float xs[8][H_];
        int t0 = bid * 8;
        #pragma unroll
        for (int r = 0; r < 8; r++) xs[r][tid] = g_TR[(t0 + r)*H_ + tid];
        __syncthreads();
        float acc[8] = {0,0,0,0,0,0,0,0};
        const float4* wr = (const float4*)(wv + (size_t)tid*H_);
        #pragma unroll 8
        for (int k4 = 0; k4 < H_/4; k4++) {
            float4 w = wr[k4];
            int k = k4 << 2;
            #pragma unroll
            for (int r = 0; r < 8; r++)
                acc[r] += xs[r][k]*w.x + xs[r][k+1]*w.y + xs[r][k+2]*w.z + xs[r][k+3]*w.w;
        }
        #pragma unroll
        for (int r = 0; r < 8; r++) g_Vtok[(t0 + r)*H_ + tid] = acc[r];
    } else if (bid < 512) {
        int tok = (bid - 256) * 8 + (tid >> 5);
        int lane = tid & 31;
        const float* tr = g_TR + (size_t)tok*H_;
        float ax = 0.f, ay = 0.f, az = 0.f, aw = 0.f;
        #pragma unroll
        for (int i = 0; i < 8; i++) {
            int c = lane + 32*i;
            float x = tr[c];
            ax += x * g_QK[0*H_ + c];
            ay += x * g_QK[1*H_ + c];
            az += x * g_QK[2*H_ + c];
            aw += x * g_QK[3*H_ + c];
        }
        #pragma unroll
        for (int o = 16; o; o >>= 1) {
            ax += __shfl_xor_sync(0xFFFFFFFFu, ax, o);
            ay += __shfl_xor_sync(0xFFFFFFFFu, ay, o);
            az += __shfl_xor_sync(0xFFFFFFFFu, az, o);
            aw += __shfl_xor_sync(0xFFFFFFFFu, aw, o);
        }
        if (lane == 0) g_Ltok[tok] = make_float4(ax, ay, az, aw);
    } else if (bid < 768) {
        int o = (bid - 512) * 256 + tid;
        __nv_bfloat16 hh, ll; split_bf16(wo[o], hh, ll);
        g_WOh[o] = hh; g_WOl[o] = ll;
    } else if (bid < 1792) {
        int o = (bid - 768) * 256 + tid;          // natural order, coalesced
        __nv_bfloat16 hh, ll; split_bf16(w1[o], hh, ll);
        g_W1h[o] = hh; g_W1l[o] = ll;
    } else {
        int o = (bid - 1792) * 256 + tid;
        __nv_bfloat16 hh, ll; split_bf16(w2[o], hh, ll);
        g_W2h[o] = hh; g_W2l[o] = ll;
    }
}

// ================= span kernel: one warp per span ============================
__global__ __launch_bounds__(256) void k_span(const int* __restrict__ span_ids,
                                              const void* __restrict__ maskp) {
    int sp = blockIdx.x * 8 + (threadIdx.x >> 5);
    int lane = threadIdx.x & 31;
    int start = span_ids[2*sp];
    int end   = span_ids[2*sp + 1];
    int len   = read_mask(maskp, sp) ? (end - start) : 0;
    int boff  = (sp >> 13) * S_;

    int w = lane & 15;
    int gt = boff + min(max(start + w, 0), S_ - 1);
    bool valid = (w < len);

    float4 L = valid ? g_Ltok[gt] : make_float4(NEGV, NEGV, NEGV, NEGV);
    float mx = L.x, my = L.y, mz = L.z, mw = L.w;
    #pragma unroll
    for (int o = 8; o; o >>= 1) {
        mx = fmaxf(mx, __shfl_xor_sync(0xFFFFFFFFu, mx, o, 16));
        my = fmaxf(my, __shfl_xor_sync(0xFFFFFFFFu, my, o, 16));
        mz = fmaxf(mz, __shfl_xor_sync(0xFFFFFFFFu, mz, o, 16));
        mw = fmaxf(mw, __shfl_xor_sync(0xFFFFFFFFu, mw, o, 16));
    }
    float ex = valid ? expf(L.x - mx) : 0.f;
    float ey = valid ? expf(L.y - my) : 0.f;
    float ez = valid ? expf(L.z - mz) : 0.f;
    float ew = valid ? expf(L.w - mw) : 0.f;
    float sx = ex, sy = ey, sz = ez, sw = ew;
    #pragma unroll
    for (int o = 8; o; o >>= 1) {
        sx += __shfl_xor_sync(0xFFFFFFFFu, sx, o, 16);
        sy += __shfl_xor_sync(0xFFFFFFFFu, sy, o, 16);
        sz += __shfl_xor_sync(0xFFFFFFFFu, sz, o, 16);
        sw += __shfl_xor_sync(0xFFFFFFFFu, sw, o, 16);
    }
    float a0 = len ? ex / sx : 0.f;
    float a1 = len ? ey / sy : 0.f;
    float a2 = len ? ez / sz : 0.f;
    float a3 = len ? ew / sw : 0.f;

    int hsel = lane >> 4;
    float acc0[4] = {0,0,0,0}, acc1[4] = {0,0,0,0};
    #pragma unroll
    for (int ww = 0; ww < MAXW; ww++) {
        int tw  = __shfl_sync(0xFFFFFFFFu, gt, ww);
        float b0 = __shfl_sync(0xFFFFFFFFu, a0, ww);
        float b1 = __shfl_sync(0xFFFFFFFFu, a1, ww);
        float b2 = __shfl_sync(0xFFFFFFFFu, a2, ww);
        float b3 = __shfl_sync(0xFFFFFFFFu, a3, ww);
        float s0 = hsel ? b1 : b0;
        float s1 = hsel ? b3 : b2;
        float4 v0 = *(const float4*)(g_Vtok + (size_t)tw*H_ + 4*lane);
        float4 v1 = *(const float4*)(g_Vtok + (size_t)tw*H_ + 128 + 4*lane);
        acc0[0] += s0*v0.x; acc0[1] += s0*v0.y; acc0[2] += s0*v0.z; acc0[3] += s0*v0.w;
        acc1[0] += s1*v1.x; acc1[1] += s1*v1.y; acc1[2] += s1*v1.z; acc1[3] += s1*v1.w;
    }
    union { __nv_bfloat16 b[4]; uint2 u; } H0, L0, H1, L1;
    #pragma unroll
    for (int e = 0; e < 4; e++) {
        split_bf16(acc0[e], H0.b[e], L0.b[e]);
        split_bf16(acc1[e], H1.b[e], L1.b[e]);
    }
    size_t base = (size_t)sp*H_ + 4*lane;
    *(uint2*)(g_Ctxh + base)       = H0.u;
    *(uint2*)(g_Ctxl + base)       = L0.u;
    *(uint2*)(g_Ctxh + base + 128) = H1.u;
    *(uint2*)(g_Ctxl + base + 128) = L1.u;
}

// ================= mma.sync bf16 GEMM, 3-term compensated ====================
// BT=0: B global [N][K] (smem [128n][40k]);  BT=1: B global [K][N] (smem [32k][136n], ldsm.trans)
#define PADK     40
#define PADN     136
#define MATSZ    (128*PADK)           // 5120 elems (A slot; B-trans uses <= this)
#define STAGEB   (4*MATSZ*2)          // 40960 B
#define NBUF     5
#define GSMEM_BYTES (NBUF*STAGEB)     // 204800

template<int BT>
__device__ __forceinline__ void stage_load(uint32_t sbase, int buf,
        const __nv_bfloat16* __restrict__ Ah, const __nv_bfloat16* __restrict__ Al,
        const __nv_bfloat16* __restrict__ Bh, const __nv_bfloat16* __restrict__ Bl,
        int row0, int col0, int K, int N, int kb, int tid) {
    uint32_t sb = sbase + buf*STAGEB;
    // A hi/lo: [128 rows][PADK]
    #pragma unroll
    for (int m = 0; m < 2; m++) {
        const __nv_bfloat16* p = m ? Al : Ah;
        #pragma unroll
        for (int half = 0; half < 2; half++) {
            int idx = tid + (half << 8);
            int row = idx >> 2, kc = idx & 3;
            cp16(sb + m*(MATSZ*2) + row*(PADK*2) + kc*16,
                 p + (size_t)(row0 + row)*K + kb + kc*8);
        }
    }
    // B hi/lo
    #pragma unroll
    for (int m = 0; m < 2; m++) {
        const __nv_bfloat16* p = m ? Bl : Bh;
        #pragma unroll
        for (int half = 0; half < 2; half++) {
            int idx = tid + (half << 8);
            if (BT == 0) {
                int row = idx >> 2, kc = idx & 3;
                cp16(sb + (2 + m)*(MATSZ*2) + row*(PADK*2) + kc*16,
                     p + (size_t)(col0 + row)*K + kb + kc*8);
            } else {
                int row = idx >> 4, nc = idx & 15;      // 32 k-rows x 16 chunks
                cp16(sb + (2 + m)*(MATSZ*2) + row*(PADN*2) + nc*16,
                     p + (size_t)(kb + row)*N + col0 + nc*8);
            }
        }
    }
    CP_COMMIT();
}

template<int EPI, int BT>
__global__ __launch_bounds__(256)
void k_gemm(const __nv_bfloat16* __restrict__ Ah, const __nv_bfloat16* __restrict__ Al,
            const __nv_bfloat16* __restrict__ Bh, const __nv_bfloat16* __restrict__ Bl,
            const float* __restrict__ bias, float* __restrict__ C,
            __nv_bfloat16* __restrict__ Oh, __nv_bfloat16* __restrict__ Ol,
            const __nv_bfloat16* __restrict__ Rh, const __nv_bfloat16* __restrict__ Rl,
            int K, int N) {
    extern __shared__ __nv_bfloat16 smem[];
    uint32_t sbase = smem_u32(smem);
    const int tid = threadIdx.x, wid = tid >> 5, lane = tid & 31;
    const int row0 = blockIdx.y * 128, col0 = blockIdx.x * 128;
    const int wm = (wid >> 2) * 64;
    const int wn = (wid & 3) * 32;
    const int NSTG = K >> 5;              // >= 8

    const uint32_t aoff  = ((lane & 15) * PADK + ((lane >> 4) << 3)) * 2;
    const uint32_t boff  = (((((lane >> 4) << 3) + (lane & 7)) * PADK) + (((lane >> 3) & 1) << 3)) * 2;
    const uint32_t btoff = ((lane & 15) * PADN + ((lane >> 4) << 3)) * 2;

    float acc[4][4][4];
    #pragma unroll
    for (int mi = 0; mi < 4; mi++)
        #pragma unroll
        for (int ni = 0; ni < 4; ni++)
            #pragma unroll
            for (int e = 0; e < 4; e++) acc[mi][ni][e] = 0.f;

    stage_load<BT>(sbase, 0, Ah, Al, Bh, Bl, row0, col0, K, N, 0,  tid);
    stage_load<BT>(sbase, 1, Ah, Al, Bh, Bl, row0, col0, K, N, 32, tid);
    stage_load<BT>(sbase, 2, Ah, Al, Bh, Bl, row0, col0, K, N, 64, tid);
    stage_load<BT>(sbase, 3, Ah, Al, Bh, Bl, row0, col0, K, N, 96, tid);

    for (int s = 0; s < NSTG; s++) {
        CP_WAIT(3);
        __syncthreads();
        uint32_t sb = sbase + (s % NBUF)*STAGEB;
        uint32_t sAh = sb,                sAl = sb + MATSZ*2;
        uint32_t sBh = sb + 2*MATSZ*2,    sBl = sb + 3*MATSZ*2;

        #pragma unroll
        for (int kk = 0; kk < 2; kk++) {
            uint32_t kby  = kk * 32;          // A: 16 elems * 2B
            uint32_t kbyt = kk * (16*PADN*2); // B-trans: 16 k-rows
            uint32_t a[4][4], bh[4][2], bl[4][2];
            #pragma unroll
            for (int mi = 0; mi < 4; mi++)
                ldsm4(a[mi][0], a[mi][1], a[mi][2], a[mi][3],
                      sAh + aoff + (wm + mi*16)*(PADK*2) + kby);
            #pragma unroll
            for (int nj = 0; nj < 2; nj++) {
                if (BT == 0)
                    ldsm4(bh[2*nj][0], bh[2*nj][1], bh[2*nj+1][0], bh[2*nj+1][1],
                          sBh + boff + (wn + nj*16)*(PADK*2) + kby);
                else
                    ldsm4t(bh[2*nj][0], bh[2*nj][1], bh[2*nj+1][0], bh[2*nj+1][1],
                           sBh + btoff + kbyt + (wn + nj*16)*2);
            }
            #pragma unroll
            for (int mi = 0; mi < 4; mi++)
                #pragma unroll
                for (int ni = 0; ni < 4; ni++)
                    mma16816(acc[mi][ni], a[mi][0], a[mi][1], a[mi][2], a[mi][3],
                             bh[ni][0], bh[ni][1]);
            #pragma unroll
            for (int nj = 0; nj < 2; nj++) {
                if (BT == 0)
                    ldsm4(bl[2*nj][0], bl[2*nj][1], bl[2*nj+1][0], bl[2*nj+1][1],
                          sBl + boff + (wn + nj*16)*(PADK*2) + kby);
                else
                    ldsm4t(bl[2*nj][0], bl[2*nj][1], bl[2*nj+1][0], bl[2*nj+1][1],
                           sBl + btoff + kbyt + (wn + nj*16)*2);
            }
            #pragma unroll
            for (int mi = 0; mi < 4; mi++)
                #pragma unroll
                for (int ni = 0; ni < 4; ni++)
                    mma16816(acc[mi][ni], a[mi][0], a[mi][1], a[mi][2], a[mi][3],
                             bl[ni][0], bl[ni][1]);
            #pragma unroll
            for (int mi = 0; mi < 4; mi++)
                ldsm4(a[mi][0], a[mi][1], a[mi][2], a[mi][3],
                      sAl + aoff + (wm + mi*16)*(PADK*2) + kby);
            #pragma unroll
            for (int mi = 0; mi < 4; mi++)
                #pragma unroll
                for (int ni = 0; ni < 4; ni++)
                    mma16816(acc[mi][ni], a[mi][0], a[mi][1], a[mi][2], a[mi][3],
                             bh[ni][0], bh[ni][1]);
        }
        int nx = s + 4;
        if (nx < NSTG) stage_load<BT>(sbase, nx % NBUF, Ah, Al, Bh, Bl, row0, col0, K, N, nx << 5, tid);
        else           CP_COMMIT();
    }

    // ---- epilogue ----
    #pragma unroll
    for (int mi = 0; mi < 4; mi++) {
        #pragma unroll
        for (int ni = 0; ni < 4; ni++) {
            int gr0 = row0 + wm + mi*16 + (lane >> 2);
            int gc  = col0 + wn + ni*8 + ((lane & 3) << 1);
            float b0 = bias[gc], b1 = bias[gc + 1];
            float v00 = acc[mi][ni][0] + b0, v01 = acc[mi][ni][1] + b1;
            float v10 = acc[mi][ni][2] + b0, v11 = acc[mi][ni][3] + b1;
            if (EPI == 0) {
                *(float2*)(C + (size_t)gr0*N + gc)       = make_float2(v00, v01);
                *(float2*)(C + (size_t)(gr0+8)*N + gc)   = make_float2(v10, v11);
            } else if (EPI == 1) {
                union { __nv_bfloat16 b[2]; uint32_t u; } h0, l0, h1, l1;
                float w00 = fmaxf(v00, 0.f), w01 = fmaxf(v01, 0.f);
                float w10 = fmaxf(v10, 0.f), w11 = fmaxf(v11, 0.f);
                split_bf16(w00, h0.b[0], l0.b[0]); split_bf16(w01, h0.b[1], l0.b[1]);
                split_bf16(w10, h1.b[0], l1.b[0]); split_bf16(w11, h1.b[1], l1.b[1]);
                *(uint32_t*)(Oh + (size_t)gr0*N + gc)     = h0.u;
                *(uint32_t*)(Ol + (size_t)gr0*N + gc)     = l0.u;
                *(uint32_t*)(Oh + (size_t)(gr0+8)*N + gc) = h1.u;
                *(uint32_t*)(Ol + (size_t)(gr0+8)*N + gc) = l1.u;
            } else {
                union { __nv_bfloat16 b[2]; uint32_t u; } rh0, rl0, rh1, rl1;
                rh0.u = *(const uint32_t*)(Rh + (size_t)gr0*N + gc);
                rl0.u = *(const uint32_t*)(Rl + (size_t)gr0*N + gc);
                rh1.u = *(const uint32_t*)(Rh + (size_t)(gr0+8)*N + gc);
                rl1.u = *(const uint32_t*)(Rl + (size_t)(gr0+8)*N + gc);
                v00 += __bfloat162float(rh0.b[0]) + __bfloat162float(rl0.b[0]);
                v01 += __bfloat162float(rh0.b[1]) + __bfloat162float(rl0.b[1]);
                v10 += __bfloat162float(rh1.b[0]) + __bfloat162float(rl1.b[0]);
                v11 += __bfloat162float(rh1.b[1]) + __bfloat162float(rl1.b[1]);
                *(float2*)(C + (size_t)gr0*N + gc)       = make_float2(v00, v01);
                *(float2*)(C + (size_t)(gr0+8)*N + gc)   = make_float2(v10, v11);
            }
        }
    }
}

// ================= LayerNorm variants =================
__global__ __launch_bounds__(256) void k_ln_bf16(const float* __restrict__ X,
        __nv_bfloat16* __restrict__ Yh, __nv_bfloat16* __restrict__ Yl,
        const float* __restrict__ g, const float* __restrict__ bb) {
    int gw = (blockIdx.x * 256 + threadIdx.x) >> 5;
    int lane = threadIdx.x & 31;
    const float* x = X + (size_t)gw * H_;
    float v[8]; float s = 0.f;
    #pragma unroll
    for (int i = 0; i < 8; i++) { v[i] = x[lane + 32*i]; s += v[i]; }
    #pragma unroll
    for (int o = 16; o; o >>= 1) s += __shfl_xor_sync(0xFFFFFFFFu, s, o);
    float mean = s * (1.f/H_);
    float sv = 0.f;
    #pragma unroll
    for (int i = 0; i < 8; i++) { float d = v[i] - mean; sv += d*d; }
    #pragma unroll
    for (int o = 16; o; o >>= 1) sv += __shfl_xor_sync(0xFFFFFFFFu, sv, o);
    float inv = rsqrtf(sv * (1.f/H_) + 1e-5f);
    #pragma unroll
    for (int i = 0; i < 8; i++) {
        int c = lane + 32*i;
        float yv = (v[i] - mean) * inv * g[c] + bb[c];
        __nv_bfloat16 hh, ll; split_bf16(yv, hh, ll);
        Yh[(size_t)gw*H_ + c] = hh;
        Yl[(size_t)gw*H_ + c] = ll;
    }
}

__global__ __launch_bounds__(256) void k_ln_final(const float* __restrict__ X, float* __restrict__ Yo,
        const float* __restrict__ g, const float* __restrict__ bb, const void* __restrict__ maskp) {
    int gw = (blockIdx.x * 256 + threadIdx.x) >> 5;
    int lane = threadIdx.x & 31;
    const float* x = X + (size_t)gw * H_;
    float v[8]; float s = 0.f;
    #pragma unroll
    for (int i = 0; i < 8; i++) { v[i] = x[lane + 32*i]; s += v[i]; }
    #pragma unroll
    for (int o = 16; o; o >>= 1) s += __shfl_xor_sync(0xFFFFFFFFu, s, o);
    float mean = s * (1.f/H_);
    float sv = 0.f;
    #pragma unroll
    for (int i = 0; i < 8; i++) { float d = v[i] - mean; sv += d*d; }
    #pragma unroll
    for (int o = 16; o; o >>= 1) sv += __shfl_xor_sync(0xFFFFFFFFu, sv, o);
    float inv = rsqrtf(sv * (1.f/H_) + 1e-5f);
    float mf = read_mask(maskp, gw) ? 1.f : 0.f;
    float* y = Yo + (size_t)gw * H_;
    #pragma unroll
    for (int i = 0; i < 8; i++) {
        int c = lane + 32*i;
        y[c] = ((v[i] - mean) * inv * g[c] + bb[c]) * mf;
    }
}

// ================= launch =================
extern "C" void kernel_launch(void* const* d_in, const int* in_sizes, int n_in,
                              void* d_out, int out_size) {
    const float* tok   = (const float*)d_in[0];
    const int*   sids  = (const int*)  d_in[1];
    const void*  masks =               d_in[2];
    const float* dq    = (const float*)d_in[4];
    const float* wq    = (const float*)d_in[5];
    const float* wk    = (const float*)d_in[6];
    const float* wv    = (const float*)d_in[7];
    const float* bqkv  = (const float*)d_in[8];
    const float* wo    = (const float*)d_in[9];
    const float* bo    = (const float*)d_in[10];
    const float* lng   = (const float*)d_in[11];
    const float* lnb   = (const float*)d_in[12];
    const float* w1    = (const float*)d_in[13];
    const float* b1    = (const float*)d_in[14];
    const float* w2    = (const float*)d_in[15];
    const float* b2    = (const float*)d_in[16];
    float* out = (float*)d_out;

    float *T1, *BO;
    __nv_bfloat16 *Ch, *Cl, *Yh, *Yl, *Fh, *Fl, *WOh, *WOl, *W1h, *W1l, *W2h, *W2l;
    cudaGetSymbolAddress((void**)&T1,  g_T1);
    cudaGetSymbolAddress((void**)&BO,  g_BO);
    cudaGetSymbolAddress((void**)&Ch,  g_Ctxh);
    cudaGetSymbolAddress((void**)&Cl,  g_Ctxl);
    cudaGetSymbolAddress((void**)&Yh,  g_Yh);
    cudaGetSymbolAddress((void**)&Yl,  g_Yl);
    cudaGetSymbolAddress((void**)&Fh,  g_Fh);
    cudaGetSymbolAddress((void**)&Fl,  g_Fl);
    cudaGetSymbolAddress((void**)&WOh, g_WOh);
    cudaGetSymbolAddress((void**)&WOl, g_WOl);
    cudaGetSymbolAddress((void**)&W1h, g_W1h);
    cudaGetSymbolAddress((void**)&W1l, g_W1l);
    cudaGetSymbolAddress((void**)&W2h, g_W2h);
    cudaGetSymbolAddress((void**)&W2l, g_W2l);

    cudaFuncSetAttribute(k_gemm<0,0>, cudaFuncAttributeMaxDynamicSharedMemorySize, GSMEM_BYTES);
    cudaFuncSetAttribute(k_gemm<1,1>, cudaFuncAttributeMaxDynamicSharedMemorySize, GSMEM_BYTES);
    cudaFuncSetAttribute(k_gemm<2,1>, cudaFuncAttributeMaxDynamicSharedMemorySize, GSMEM_BYTES);

    k_init<<<2050, 256>>>(tok, (const unsigned int*)masks, dq, wq, wk, bqkv, wo, bo);
    k_prep<<<2816, 256>>>(wv, wo, w1, w2);
    k_span<<<NSPAN/8, 256>>>(sids, masks);

    // GEMM1: T1 = Ctx(32768x256) @ WO^T (N=256) + BO        [B = [N][K], non-trans]
    k_gemm<0,0><<<dim3(2, NSPAN/128), 256, GSMEM_BYTES>>>(Ch, Cl, WOh, WOl, BO, T1,
                                                          nullptr, nullptr, nullptr, nullptr, H_, H_);
    // Y = LN(T1) -> bf16 hi/lo
    k_ln_bf16<<<NSPAN/8, 256>>>(T1, Yh, Yl, lng, lnb);
    // GEMM2: F = relu(Y @ w1 + b1) -> bf16 hi/lo            [B = w1 [K=256][N=1024], trans]
    k_gemm<1,1><<<dim3(8, NSPAN/128), 256, GSMEM_BYTES>>>(Yh, Yl, W1h, W1l, b1, nullptr,
                                                          Fh, Fl, nullptr, nullptr, H_, FF_);
    // GEMM3: T1 = F @ w2 + b2 + Y                           [B = w2 [K=1024][N=256], trans]
    k_gemm<2,1><<<dim3(2, NSPAN/128), 256, GSMEM_BYTES>>>(Fh, Fl, W2h, W2l, b2, T1,
                                                          nullptr, nullptr, Yh, Yl, FF_, H_);
    // out = LN(T1) * mask
    k_ln_final<<<NSPAN/8, 256>>>(T1, out, lng, lnb, masks);
}